// round 15
// baseline (speedup 1.0000x reference)
#include <cuda_runtime.h>
#include <cuda_fp16.h>
#include <cstdint>

#define N_NODES 100000
#define E_EDGES 1600000
#define F_IN    512
#define F_HID   128
#define F_OUT   40

// Scratch (allocation-free rule: __device__ globals)
__device__ uint32_t g_m1h[(size_t)N_NODES * 64];   // X@W1 as half2-packed fp16
__device__ float g_agg1[(size_t)N_NODES * F_HID];  // relu(scatter-sum + b1), fp32
__device__ uint32_t g_m2h[(size_t)N_NODES * 20];   // h@W2 as half2-packed fp16

// W1 fp16, pair-packed: [k2][n] uint32 = (fp16(W[2k2][n]), fp16(W[2k2+1][n]))
__device__ uint32_t g_w1h[256 * 128];
// W2 fp16, [n][k2] pair-packed
__device__ uint32_t g_w2h[40 * 64];

// CSR binning scratch (rebuilt every launch)
__device__ int   g_deg[N_NODES];
__device__ int   g_off[N_NODES];
__device__ int   g_cur[N_NODES];
__device__ int   g_bsum[128];
__device__ int   g_bscan[128];
__device__ int   g_esrc[E_EDGES];
__device__ float g_ewp[E_EDGES];

// ============================================================================
// helpers
// ============================================================================
__device__ __forceinline__ void mma16816h(float* d, const uint32_t* a,
                                          uint32_t b0, uint32_t b1) {
    asm volatile(
        "mma.sync.aligned.m16n8k16.row.col.f32.f16.f16.f32 "
        "{%0,%1,%2,%3}, {%4,%5,%6,%7}, {%8,%9}, {%0,%1,%2,%3};"
        : "+f"(d[0]), "+f"(d[1]), "+f"(d[2]), "+f"(d[3])
        : "r"(a[0]), "r"(a[1]), "r"(a[2]), "r"(a[3]), "r"(b0), "r"(b1));
}

__device__ __forceinline__ void ldmx4(uint32_t* r, uint32_t addr) {
    asm volatile(
        "ldmatrix.sync.aligned.m8n8.x4.shared.b16 {%0,%1,%2,%3}, [%4];"
        : "=r"(r[0]), "=r"(r[1]), "=r"(r[2]), "=r"(r[3]) : "r"(addr));
}
__device__ __forceinline__ void ldmx2(uint32_t* r, uint32_t addr) {
    asm volatile(
        "ldmatrix.sync.aligned.m8n8.x2.shared.b16 {%0,%1}, [%2];"
        : "=r"(r[0]), "=r"(r[1]) : "r"(addr));
}

// fp16 hi/lo split of a pair of floats (packed half2 as uint32)
__device__ __forceinline__ void split2h(float x, float y,
                                        uint32_t& hi, uint32_t& lo) {
    __half2 h = __floats2half2_rn(x, y);
    float hx = __half2float(__low2half(h)), hy = __half2float(__high2half(h));
    __half2 l = __floats2half2_rn(x - hx, y - hy);
    hi = *(uint32_t*)&h;
    lo = *(uint32_t*)&l;
}

// ============================================================================
// prep_w1 / prep_w2: one-time fp16 packing of weights
// ============================================================================
__global__ __launch_bounds__(256) void prep_w1(const float* __restrict__ W1) {
    int i = blockIdx.x * 256 + threadIdx.x;   // i = k2*128 + n
    int k2 = i >> 7, n = i & 127;
    float w0 = W1[(size_t)(2 * k2) * F_HID + n];
    float w1 = W1[(size_t)(2 * k2 + 1) * F_HID + n];
    __half2 h = __floats2half2_rn(w0, w1);
    g_w1h[i] = *(uint32_t*)&h;
}

__global__ __launch_bounds__(256) void prep_w2(const float* __restrict__ W2) {
    int i = blockIdx.x * 256 + threadIdx.x;   // i = n*64 + k2
    if (i >= 40 * 64) return;
    int n = i >> 6, k2 = i & 63;
    float w0 = W2[(size_t)(2 * k2) * F_OUT + n];
    float w1 = W2[(size_t)(2 * k2 + 1) * F_OUT + n];
    __half2 h = __floats2half2_rn(w0, w1);
    g_w2h[i] = *(uint32_t*)&h;
}

// ============================================================================
// GEMM1 (mma.sync fp16 single-term): m1h[N,128] = fp16(X)[N,512] @ fp16(W1)
// Block 128x128, BK=32, 8 warps (4m x 2n), sw-pipelined LDG, ldmatrix frags.
// ============================================================================
#define A_STRIDE 40   // 80B rows -> ldmatrix 8-row groups hit distinct banks
#define B_STRIDE 40

__global__ __launch_bounds__(256) void gemm1_mma(const float* __restrict__ X) {
    __shared__ __align__(16) unsigned short Ahi[128 * A_STRIDE];
    __shared__ __align__(16) unsigned short Bh[128 * B_STRIDE];

    int tid = threadIdx.x;
    int wid = tid >> 5, lane = tid & 31;
    int warp_m = wid >> 1;
    int warp_n = wid & 1;
    int mBase = blockIdx.x * 128;

    uint32_t sAhi = (uint32_t)__cvta_generic_to_shared(Ahi);
    uint32_t sBh  = (uint32_t)__cvta_generic_to_shared(Bh);

    int aRow = tid >> 3, aK4 = tid & 7;
    bool aValid[4];
    const float* aPtr[4];
    #pragma unroll
    for (int i = 0; i < 4; i++) {
        int row = aRow + 32 * i;
        int grow = mBase + row;
        aValid[i] = grow < N_NODES;
        aPtr[i] = X + (size_t)(aValid[i] ? grow : 0) * F_IN + aK4 * 4;
    }
    int bN = tid & 127, bK2 = tid >> 7;
    int g4 = lane >> 3, r8 = lane & 7;

    float acc[2][8][4];
    #pragma unroll
    for (int mt = 0; mt < 2; mt++)
        #pragma unroll
        for (int nt = 0; nt < 8; nt++)
            #pragma unroll
            for (int i = 0; i < 4; i++) acc[mt][nt][i] = 0.f;

    float4 aReg[4];
    uint32_t bReg[8];
    #pragma unroll
    for (int i = 0; i < 4; i++)
        aReg[i] = aValid[i] ? *(const float4*)(aPtr[i])
                            : make_float4(0.f, 0.f, 0.f, 0.f);
    #pragma unroll
    for (int i = 0; i < 8; i++)
        bReg[i] = g_w1h[(bK2 + 2 * i) * 128 + bN];

    for (int stage = 0; stage < 16; stage++) {
        #pragma unroll
        for (int i = 0; i < 4; i++) {
            __half2 h0 = __floats2half2_rn(aReg[i].x, aReg[i].y);
            __half2 h1 = __floats2half2_rn(aReg[i].z, aReg[i].w);
            int si = (aRow + 32 * i) * A_STRIDE + aK4 * 4;
            *(uint2*)&Ahi[si] = make_uint2(*(uint32_t*)&h0, *(uint32_t*)&h1);
        }
        #pragma unroll
        for (int i = 0; i < 8; i++) {
            int si = bN * B_STRIDE + 2 * (bK2 + 2 * i);
            *(uint32_t*)&Bh[si] = bReg[i];
        }
        __syncthreads();

        if (stage < 15) {
            int kBase = (stage + 1) * 32;
            #pragma unroll
            for (int i = 0; i < 4; i++)
                aReg[i] = aValid[i] ? *(const float4*)(aPtr[i] + kBase)
                                    : make_float4(0.f, 0.f, 0.f, 0.f);
            #pragma unroll
            for (int i = 0; i < 8; i++)
                bReg[i] = g_w1h[(kBase / 2 + bK2 + 2 * i) * 128 + bN];
        }

        #pragma unroll
        for (int ks = 0; ks < 2; ks++) {
            int kk = ks * 16;
            int aSrcRow = (g4 & 1) * 8 + r8;
            int aSrcCol = kk + (g4 >> 1) * 8;
            uint32_t ah[2][4];
            #pragma unroll
            for (int mt = 0; mt < 2; mt++) {
                uint32_t off = ((warp_m * 32 + mt * 16 + aSrcRow) * A_STRIDE + aSrcCol) * 2;
                ldmx4(ah[mt], sAhi + off);
            }
            int bSrcN = (g4 >> 1) * 8 + r8;
            int bSrcK = kk + (g4 & 1) * 8;
            #pragma unroll
            for (int nt2 = 0; nt2 < 4; nt2++) {
                uint32_t b[4];
                uint32_t off = ((warp_n * 64 + nt2 * 16 + bSrcN) * B_STRIDE + bSrcK) * 2;
                ldmx4(b, sBh + off);
                #pragma unroll
                for (int mt = 0; mt < 2; mt++) {
                    mma16816h(acc[mt][2 * nt2 + 0], ah[mt], b[0], b[1]);
                    mma16816h(acc[mt][2 * nt2 + 1], ah[mt], b[2], b[3]);
                }
            }
        }
        __syncthreads();
    }

    // epilogue: pack to fp16 half2, store u32
    int g = lane >> 2, tg = lane & 3;
    #pragma unroll
    for (int mt = 0; mt < 2; mt++) {
        int r0 = mBase + warp_m * 32 + mt * 16 + g;
        int r1 = r0 + 8;
        #pragma unroll
        for (int nt = 0; nt < 8; nt++) {
            int col2 = warp_n * 32 + nt * 4 + tg;   // u32 index within row
            __half2 p0 = __floats2half2_rn(acc[mt][nt][0], acc[mt][nt][1]);
            __half2 p1 = __floats2half2_rn(acc[mt][nt][2], acc[mt][nt][3]);
            if (r0 < N_NODES) g_m1h[(size_t)r0 * 64 + col2] = *(uint32_t*)&p0;
            if (r1 < N_NODES) g_m1h[(size_t)r1 * 64 + col2] = *(uint32_t*)&p1;
        }
    }
}

// ============================================================================
// CSR binning: histogram -> exclusive scan -> placement
// ============================================================================
__global__ __launch_bounds__(256) void bin_count(const int* __restrict__ ei) {
    int e = blockIdx.x * 256 + threadIdx.x;
    if (e < E_EDGES) atomicAdd(&g_deg[ei[E_EDGES + e]], 1);
}

__global__ __launch_bounds__(256) void scanA() {
    __shared__ int wsum[8];
    int t = threadIdx.x;
    int base = blockIdx.x * 1024 + t * 4;
    int v[4];
    #pragma unroll
    for (int i = 0; i < 4; i++)
        v[i] = (base + i < N_NODES) ? g_deg[base + i] : 0;
    int s = v[0] + v[1] + v[2] + v[3];
    int lane = t & 31, w = t >> 5;
    int inc = s;
    #pragma unroll
    for (int o = 1; o < 32; o <<= 1) {
        int n = __shfl_up_sync(0xFFFFFFFFu, inc, o);
        if (lane >= o) inc += n;
    }
    if (lane == 31) wsum[w] = inc;
    __syncthreads();
    if (t == 0) {
        int run = 0;
        #pragma unroll
        for (int i = 0; i < 8; i++) { int x = wsum[i]; wsum[i] = run; run += x; }
        g_bsum[blockIdx.x] = run;
    }
    __syncthreads();
    int excl = inc - s + wsum[w];
    int o0 = excl, o1 = o0 + v[0], o2 = o1 + v[1], o3 = o2 + v[2];
    if (base + 0 < N_NODES) g_off[base + 0] = o0;
    if (base + 1 < N_NODES) g_off[base + 1] = o1;
    if (base + 2 < N_NODES) g_off[base + 2] = o2;
    if (base + 3 < N_NODES) g_off[base + 3] = o3;
}

__global__ __launch_bounds__(128) void scanB(int nb) {
    __shared__ int ws[4];
    int t = threadIdx.x;
    int v = (t < nb) ? g_bsum[t] : 0;
    int lane = t & 31, w = t >> 5;
    int inc = v;
    #pragma unroll
    for (int o = 1; o < 32; o <<= 1) {
        int n = __shfl_up_sync(0xFFFFFFFFu, inc, o);
        if (lane >= o) inc += n;
    }
    if (lane == 31) ws[w] = inc;
    __syncthreads();
    if (t == 0) {
        int run = 0;
        #pragma unroll
        for (int i = 0; i < 4; i++) { int x = ws[i]; ws[i] = run; run += x; }
    }
    __syncthreads();
    if (t < nb) g_bscan[t] = inc - v + ws[w];
}

__global__ __launch_bounds__(256) void scanC() {
    int add = g_bscan[blockIdx.x];
    int base = blockIdx.x * 1024 + threadIdx.x;
    #pragma unroll
    for (int i = 0; i < 4; i++) {
        int idx = base + i * 256;
        if (idx < N_NODES) {
            int val = g_off[idx] + add;
            g_off[idx] = val;
            g_cur[idx] = val;
        }
    }
}

__global__ __launch_bounds__(256) void bin_fill(const int* __restrict__ ei,
                                                const float* __restrict__ ew) {
    int e = blockIdx.x * 256 + threadIdx.x;
    if (e >= E_EDGES) return;
    int src = ei[e];
    int dst = ei[E_EDGES + e];
    int pos = atomicAdd(&g_cur[dst], 1);
    g_esrc[pos] = src;
    g_ewp[pos] = ew[e];
}

// ============================================================================
// Agg1 (dst-driven, fused b1+relu), fp16 m1 gather, 4-deep unroll
// ============================================================================
__global__ __launch_bounds__(256) void agg1_kernel(const float* __restrict__ b1) {
    int wv = blockIdx.x * 8 + (threadIdx.x >> 5);
    int lane = threadIdx.x & 31;
    if (wv >= N_NODES) return;
    int beg = g_off[wv];
    int end = (wv == N_NODES - 1) ? E_EDGES : g_off[wv + 1];

    float4 a0 = make_float4(0.f, 0.f, 0.f, 0.f);
    float4 a1 = make_float4(0.f, 0.f, 0.f, 0.f);
    float4 a2 = make_float4(0.f, 0.f, 0.f, 0.f);
    float4 a3 = make_float4(0.f, 0.f, 0.f, 0.f);
    int j = beg;
    for (; j + 4 <= end; j += 4) {
        int s0 = g_esrc[j], s1 = g_esrc[j + 1], s2 = g_esrc[j + 2], s3 = g_esrc[j + 3];
        float w0 = g_ewp[j], w1 = g_ewp[j + 1], w2 = g_ewp[j + 2], w3 = g_ewp[j + 3];
        uint2 q0 = ((const uint2*)(g_m1h + (size_t)s0 * 64))[lane];
        uint2 q1 = ((const uint2*)(g_m1h + (size_t)s1 * 64))[lane];
        uint2 q2 = ((const uint2*)(g_m1h + (size_t)s2 * 64))[lane];
        uint2 q3 = ((const uint2*)(g_m1h + (size_t)s3 * 64))[lane];
        float2 u, v;
        u = __half22float2(*(__half2*)&q0.x); v = __half22float2(*(__half2*)&q0.y);
        a0.x += u.x * w0; a0.y += u.y * w0; a0.z += v.x * w0; a0.w += v.y * w0;
        u = __half22float2(*(__half2*)&q1.x); v = __half22float2(*(__half2*)&q1.y);
        a1.x += u.x * w1; a1.y += u.y * w1; a1.z += v.x * w1; a1.w += v.y * w1;
        u = __half22float2(*(__half2*)&q2.x); v = __half22float2(*(__half2*)&q2.y);
        a2.x += u.x * w2; a2.y += u.y * w2; a2.z += v.x * w2; a2.w += v.y * w2;
        u = __half22float2(*(__half2*)&q3.x); v = __half22float2(*(__half2*)&q3.y);
        a3.x += u.x * w3; a3.y += u.y * w3; a3.z += v.x * w3; a3.w += v.y * w3;
    }
    for (; j < end; j++) {
        int s0 = g_esrc[j];
        float w0 = g_ewp[j];
        uint2 q0 = ((const uint2*)(g_m1h + (size_t)s0 * 64))[lane];
        float2 u = __half22float2(*(__half2*)&q0.x);
        float2 v = __half22float2(*(__half2*)&q0.y);
        a0.x += u.x * w0; a0.y += u.y * w0; a0.z += v.x * w0; a0.w += v.y * w0;
    }
    float4 bb = ((const float4*)b1)[lane];
    float4 r;
    r.x = fmaxf(a0.x + a1.x + a2.x + a3.x + bb.x, 0.f);
    r.y = fmaxf(a0.y + a1.y + a2.y + a3.y + bb.y, 0.f);
    r.z = fmaxf(a0.z + a1.z + a2.z + a3.z + bb.z, 0.f);
    r.w = fmaxf(a0.w + a1.w + a2.w + a3.w + bb.w, 0.f);
    ((float4*)(g_agg1 + (size_t)wv * F_HID))[lane] = r;
}

// ============================================================================
// GEMM2 (mma fp16 2-term A): m2h[N,40] = agg1 @ W2[128,40], fp16 output
// ============================================================================
#define G2K 136   // smem row stride in shorts (272B: 8-row groups conflict-free)
#define G2M_SMEM ((2 * 128 * G2K + 40 * G2K) * 2)

__global__ __launch_bounds__(256) void gemm2_mma() {
    extern __shared__ unsigned short g2sm[];
    unsigned short* Ahi = g2sm;                    // [128][G2K]
    unsigned short* Alo = g2sm + 128 * G2K;
    uint32_t* Bh32 = (uint32_t*)(g2sm + 2 * 128 * G2K);   // [40][G2K/2]

    int tid = threadIdx.x, wid = tid >> 5, lane = tid & 31;
    int rowBase = blockIdx.x * 128;

    #pragma unroll
    for (int i = 0; i < 10; i++) {
        int idx = tid + 256 * i;
        int n = idx >> 6, k2 = idx & 63;
        Bh32[n * (G2K / 2) + k2] = g_w2h[idx];
    }
    #pragma unroll
    for (int i = 0; i < 16; i++) {
        int idx = tid + 256 * i;            // 4096 float4s
        int r = idx >> 5, k4 = idx & 31;
        int row = rowBase + r;
        float4 v = make_float4(0.f, 0.f, 0.f, 0.f);
        if (row < N_NODES)
            v = ((const float4*)(g_agg1 + (size_t)row * F_HID))[k4];
        uint32_t h0, l0, h1, l1;
        split2h(v.x, v.y, h0, l0);
        split2h(v.z, v.w, h1, l1);
        int si = r * G2K + k4 * 4;
        *(uint2*)&Ahi[si] = make_uint2(h0, h1);
        *(uint2*)&Alo[si] = make_uint2(l0, l1);
    }
    __syncthreads();

    uint32_t sbase = (uint32_t)__cvta_generic_to_shared(g2sm);
    uint32_t sAhi = sbase;
    uint32_t sAlo = sbase + 128 * G2K * 2;
    uint32_t sBh  = sbase + 2 * 128 * G2K * 2;

    float acc[5][4];
    #pragma unroll
    for (int nt = 0; nt < 5; nt++)
        #pragma unroll
        for (int i = 0; i < 4; i++) acc[nt][i] = 0.f;

    int g4 = lane >> 3, r8 = lane & 7;
    int aSrcRow = (g4 & 1) * 8 + r8;
    int aColSel = (g4 >> 1) * 8;
    int bSrcN = (g4 >> 1) * 8 + r8;
    int bKSel = (g4 & 1) * 8;
    int b2N = lane & 7, b2KSel = ((lane >> 3) & 1) * 8;

    #pragma unroll
    for (int ks = 0; ks < 8; ks++) {
        int kk = ks * 16;
        uint32_t ah[4], al[4];
        uint32_t aoff = ((wid * 16 + aSrcRow) * G2K + kk + aColSel) * 2;
        ldmx4(ah, sAhi + aoff);
        ldmx4(al, sAlo + aoff);
        uint32_t b[4];
        uint32_t boff = ((bSrcN) * G2K + kk + bKSel) * 2;
        ldmx4(b, sBh + boff);
        mma16816h(acc[0], ah, b[0], b[1]);
        mma16816h(acc[0], al, b[0], b[1]);
        mma16816h(acc[1], ah, b[2], b[3]);
        mma16816h(acc[1], al, b[2], b[3]);
        boff = ((16 + bSrcN) * G2K + kk + bKSel) * 2;
        ldmx4(b, sBh + boff);
        mma16816h(acc[2], ah, b[0], b[1]);
        mma16816h(acc[2], al, b[0], b[1]);
        mma16816h(acc[3], ah, b[2], b[3]);
        mma16816h(acc[3], al, b[2], b[3]);
        uint32_t b2[2];
        uint32_t boff2 = ((32 + b2N) * G2K + kk + b2KSel) * 2;
        ldmx2(b2, sBh + boff2);
        mma16816h(acc[4], ah, b2[0], b2[1]);
        mma16816h(acc[4], al, b2[0], b2[1]);
    }

    int g = lane >> 2, tg = lane & 3;
    int r0 = rowBase + wid * 16 + g, r1 = r0 + 8;
    #pragma unroll
    for (int nt = 0; nt < 5; nt++) {
        int col2 = nt * 4 + tg;   // u32 index within 20-u32 row
        __half2 p0 = __floats2half2_rn(acc[nt][0], acc[nt][1]);
        __half2 p1 = __floats2half2_rn(acc[nt][2], acc[nt][3]);
        if (r0 < N_NODES) g_m2h[(size_t)r0 * 20 + col2] = *(uint32_t*)&p0;
        if (r1 < N_NODES) g_m2h[(size_t)r1 * 20 + col2] = *(uint32_t*)&p1;
    }
}

// ============================================================================
// Agg2 + b2 + log_softmax fused (dst-driven), fp16 m2 gather, 4-deep unroll
// ============================================================================
__global__ __launch_bounds__(256) void agg2_ls_kernel(const float* __restrict__ b2,
                                                      float* __restrict__ out) {
    int wv = blockIdx.x * 8 + (threadIdx.x >> 5);
    int lane = threadIdx.x & 31;
    if (wv >= N_NODES) return;
    int beg = g_off[wv];
    int end = (wv == N_NODES - 1) ? E_EDGES : g_off[wv + 1];
    bool act = lane < 10;

    float4 a0 = make_float4(0.f, 0.f, 0.f, 0.f);
    float4 a1 = make_float4(0.f, 0.f, 0.f, 0.f);
    float4 a2 = make_float4(0.f, 0.f, 0.f, 0.f);
    float4 a3 = make_float4(0.f, 0.f, 0.f, 0.f);
    int j = beg;
    for (; j + 4 <= end; j += 4) {
        int s0 = g_esrc[j], s1 = g_esrc[j + 1], s2 = g_esrc[j + 2], s3 = g_esrc[j + 3];
        float w0 = g_ewp[j], w1 = g_ewp[j + 1], w2 = g_ewp[j + 2], w3 = g_ewp[j + 3];
        if (act) {
            uint2 q0 = ((const uint2*)(g_m2h + (size_t)s0 * 20))[lane];
            uint2 q1 = ((const uint2*)(g_m2h + (size_t)s1 * 20))[lane];
            uint2 q2 = ((const uint2*)(g_m2h + (size_t)s2 * 20))[lane];
            uint2 q3 = ((const uint2*)(g_m2h + (size_t)s3 * 20))[lane];
            float2 u, v;
            u = __half22float2(*(__half2*)&q0.x); v = __half22float2(*(__half2*)&q0.y);
            a0.x += u.x * w0; a0.y += u.y * w0; a0.z += v.x * w0; a0.w += v.y * w0;
            u = __half22float2(*(__half2*)&q1.x); v = __half22float2(*(__half2*)&q1.y);
            a1.x += u.x * w1; a1.y += u.y * w1; a1.z += v.x * w1; a1.w += v.y * w1;
            u = __half22float2(*(__half2*)&q2.x); v = __half22float2(*(__half2*)&q2.y);
            a2.x += u.x * w2; a2.y += u.y * w2; a2.z += v.x * w2; a2.w += v.y * w2;
            u = __half22float2(*(__half2*)&q3.x); v = __half22float2(*(__half2*)&q3.y);
            a3.x += u.x * w3; a3.y += u.y * w3; a3.z += v.x * w3; a3.w += v.y * w3;
        }
    }
    for (; j < end; j++) {
        int s0 = g_esrc[j];
        float w0 = g_ewp[j];
        if (act) {
            uint2 q0 = ((const uint2*)(g_m2h + (size_t)s0 * 20))[lane];
            float2 u = __half22float2(*(__half2*)&q0.x);
            float2 v = __half22float2(*(__half2*)&q0.y);
            a0.x += u.x * w0; a0.y += u.y * w0; a0.z += v.x * w0; a0.w += v.y * w0;
        }
    }
    float4 x = make_float4(a0.x + a1.x + a2.x + a3.x, a0.y + a1.y + a2.y + a3.y,
                           a0.z + a1.z + a2.z + a3.z, a0.w + a1.w + a2.w + a3.w);
    if (act) {
        float4 bb = ((const float4*)b2)[lane];
        x.x += bb.x; x.y += bb.y; x.z += bb.z; x.w += bb.w;
    }

    float m = act ? fmaxf(fmaxf(x.x, x.y), fmaxf(x.z, x.w)) : -1e30f;
    #pragma unroll
    for (int o = 16; o; o >>= 1) m = fmaxf(m, __shfl_xor_sync(0xFFFFFFFFu, m, o));

    float s = act ? (__expf(x.x - m) + __expf(x.y - m) +
                     __expf(x.z - m) + __expf(x.w - m)) : 0.f;
    #pragma unroll
    for (int o = 16; o; o >>= 1) s += __shfl_xor_sync(0xFFFFFFFFu, s, o);

    float lse = m + __logf(s);
    if (act) {
        x.x -= lse; x.y -= lse; x.z -= lse; x.w -= lse;
        ((float4*)(out + (size_t)wv * F_OUT))[lane] = x;
    }
}

// ============================================================================
extern "C" void kernel_launch(void* const* d_in, const int* in_sizes, int n_in,
                              void* d_out, int out_size) {
    const float* X   = (const float*)d_in[0];        // [100000,512]
    const int*   EI  = (const int*)d_in[1];          // [2,1600000] int32
    const float* EW  = (const float*)d_in[2];        // [1600000]
    const float* W1  = (const float*)d_in[3];        // [512,128]
    const float* B1  = (const float*)d_in[4];        // [128]
    const float* W2  = (const float*)d_in[5];        // [128,40]
    const float* B2  = (const float*)d_in[6];        // [40]
    float*       OUT = (float*)d_out;                // [100000,40]

    // one-time setup (first call is outside graph capture)
    static cudaStream_t s2 = nullptr;
    static cudaEvent_t evFork = nullptr, evJoin = nullptr;
    if (!s2) {
        cudaStreamCreateWithFlags(&s2, cudaStreamNonBlocking);
        cudaEventCreateWithFlags(&evFork, cudaEventDisableTiming);
        cudaEventCreateWithFlags(&evJoin, cudaEventDisableTiming);
        cudaFuncSetAttribute(gemm2_mma,
                             cudaFuncAttributeMaxDynamicSharedMemorySize, G2M_SMEM);
    }

    const int NB_SCAN = (N_NODES + 1023) / 1024;     // 98
    const int EB = E_EDGES / 256;                    // 6250 (exact)

    void* degPtr = nullptr;
    cudaGetSymbolAddress(&degPtr, g_deg);

    // ---- fork: CSR binning on s2, overlapped with gemm1 on stream 0 ----
    cudaEventRecord(evFork, 0);
    cudaStreamWaitEvent(s2, evFork, 0);

    cudaMemsetAsync(degPtr, 0, N_NODES * sizeof(int), s2);
    bin_count<<<EB, 256, 0, s2>>>(EI);
    scanA<<<NB_SCAN, 256, 0, s2>>>();
    scanB<<<1, 128, 0, s2>>>(NB_SCAN);
    scanC<<<NB_SCAN, 256, 0, s2>>>();
    bin_fill<<<EB, 256, 0, s2>>>(EI, EW);
    cudaEventRecord(evJoin, s2);

    // stream 0: weight prep + GEMM1 (independent of binning)
    prep_w1<<<128, 256>>>(W1);
    prep_w2<<<10, 256>>>(W2);
    gemm1_mma<<<(N_NODES + 127) / 128, 256>>>(X);

    // ---- join ----
    cudaStreamWaitEvent(0, evJoin, 0);

    // Agg1 (fused b1 + relu): agg1 = relu(S(m1) + b1)
    agg1_kernel<<<(N_NODES + 7) / 8, 256>>>(B1);

    // GEMM2 (tensor): m2 = agg1 @ W2, fp16 out
    gemm2_mma<<<(N_NODES + 127) / 128, 256, G2M_SMEM>>>();

    // Agg2 + b2 + log_softmax fused, writes d_out
    agg2_ls_kernel<<<(N_NODES + 7) / 8, 256>>>(B2, OUT);
}

// round 16
// speedup vs baseline: 1.2070x; 1.2070x over previous
#include <cuda_runtime.h>
#include <cuda_fp16.h>
#include <cstdint>

#define N_NODES 100000
#define E_EDGES 1600000
#define F_IN    512
#define F_HID   128
#define F_OUT   40

// Scratch (allocation-free rule: __device__ globals)
__device__ uint32_t g_m1h[(size_t)N_NODES * 64];   // X@W1 as half2-packed fp16
__device__ float g_agg1[(size_t)N_NODES * F_HID];  // relu(scatter-sum + b1), fp32
__device__ uint32_t g_m2h[(size_t)N_NODES * 20];   // h@W2 as half2-packed fp16

// W1 fp16, pair-packed: [k2][n] uint32 = (fp16(W[2k2][n]), fp16(W[2k2+1][n]))
__device__ uint32_t g_w1h[256 * 128];
// W2 fp16, [n][k2] pair-packed
__device__ uint32_t g_w2h[40 * 64];

// CSR binning scratch (rebuilt every launch)
__device__ int   g_deg[N_NODES];
__device__ int   g_off[N_NODES];
__device__ int   g_cur[N_NODES];
__device__ int   g_bsum[128];
__device__ int   g_bscan[128];
__device__ int   g_esrc[E_EDGES];
__device__ float g_ewp[E_EDGES];

// ============================================================================
// helpers
// ============================================================================
__device__ __forceinline__ void mma16816h(float* d, const uint32_t* a,
                                          uint32_t b0, uint32_t b1) {
    asm volatile(
        "mma.sync.aligned.m16n8k16.row.col.f32.f16.f16.f32 "
        "{%0,%1,%2,%3}, {%4,%5,%6,%7}, {%8,%9}, {%0,%1,%2,%3};"
        : "+f"(d[0]), "+f"(d[1]), "+f"(d[2]), "+f"(d[3])
        : "r"(a[0]), "r"(a[1]), "r"(a[2]), "r"(a[3]), "r"(b0), "r"(b1));
}

__device__ __forceinline__ void ldmx4(uint32_t* r, uint32_t addr) {
    asm volatile(
        "ldmatrix.sync.aligned.m8n8.x4.shared.b16 {%0,%1,%2,%3}, [%4];"
        : "=r"(r[0]), "=r"(r[1]), "=r"(r[2]), "=r"(r[3]) : "r"(addr));
}
__device__ __forceinline__ void ldmx2(uint32_t* r, uint32_t addr) {
    asm volatile(
        "ldmatrix.sync.aligned.m8n8.x2.shared.b16 {%0,%1}, [%2];"
        : "=r"(r[0]), "=r"(r[1]) : "r"(addr));
}

// fp16 hi/lo split of a pair of floats (packed half2 as uint32)
__device__ __forceinline__ void split2h(float x, float y,
                                        uint32_t& hi, uint32_t& lo) {
    __half2 h = __floats2half2_rn(x, y);
    float hx = __half2float(__low2half(h)), hy = __half2float(__high2half(h));
    __half2 l = __floats2half2_rn(x - hx, y - hy);
    hi = *(uint32_t*)&h;
    lo = *(uint32_t*)&l;
}

// ============================================================================
// prep_w1 / prep_w2: one-time fp16 packing of weights
// ============================================================================
__global__ __launch_bounds__(256) void prep_w1(const float* __restrict__ W1) {
    int i = blockIdx.x * 256 + threadIdx.x;   // i = k2*128 + n
    int k2 = i >> 7, n = i & 127;
    float w0 = W1[(size_t)(2 * k2) * F_HID + n];
    float w1 = W1[(size_t)(2 * k2 + 1) * F_HID + n];
    __half2 h = __floats2half2_rn(w0, w1);
    g_w1h[i] = *(uint32_t*)&h;
}

__global__ __launch_bounds__(256) void prep_w2(const float* __restrict__ W2) {
    int i = blockIdx.x * 256 + threadIdx.x;   // i = n*64 + k2
    if (i >= 40 * 64) return;
    int n = i >> 6, k2 = i & 63;
    float w0 = W2[(size_t)(2 * k2) * F_OUT + n];
    float w1 = W2[(size_t)(2 * k2 + 1) * F_OUT + n];
    __half2 h = __floats2half2_rn(w0, w1);
    g_w2h[i] = *(uint32_t*)&h;
}

// ============================================================================
// GEMM1 (mma.sync fp16, 2-term split): m1h[N,128] = X[N,512] @ W1[512,128]
// Block 128x128, BK=32, 8 warps (4m x 2n), sw-pipelined LDG, ldmatrix frags.
// D = Ahi*Bh + Alo*Bh   (round-14 proven configuration)
// ============================================================================
#define A_STRIDE 40   // 80B rows -> ldmatrix 8-row groups hit distinct banks
#define B_STRIDE 40

__global__ __launch_bounds__(256) void gemm1_mma(const float* __restrict__ X) {
    __shared__ __align__(16) unsigned short Ahi[128 * A_STRIDE];
    __shared__ __align__(16) unsigned short Alo[128 * A_STRIDE];
    __shared__ __align__(16) unsigned short Bh[128 * B_STRIDE];

    int tid = threadIdx.x;
    int wid = tid >> 5, lane = tid & 31;
    int warp_m = wid >> 1;
    int warp_n = wid & 1;
    int mBase = blockIdx.x * 128;

    uint32_t sAhi = (uint32_t)__cvta_generic_to_shared(Ahi);
    uint32_t sAlo = (uint32_t)__cvta_generic_to_shared(Alo);
    uint32_t sBh  = (uint32_t)__cvta_generic_to_shared(Bh);

    int aRow = tid >> 3, aK4 = tid & 7;
    bool aValid[4];
    const float* aPtr[4];
    #pragma unroll
    for (int i = 0; i < 4; i++) {
        int row = aRow + 32 * i;
        int grow = mBase + row;
        aValid[i] = grow < N_NODES;
        aPtr[i] = X + (size_t)(aValid[i] ? grow : 0) * F_IN + aK4 * 4;
    }
    int bN = tid & 127, bK2 = tid >> 7;
    int g4 = lane >> 3, r8 = lane & 7;

    float acc[2][8][4];
    #pragma unroll
    for (int mt = 0; mt < 2; mt++)
        #pragma unroll
        for (int nt = 0; nt < 8; nt++)
            #pragma unroll
            for (int i = 0; i < 4; i++) acc[mt][nt][i] = 0.f;

    float4 aReg[4];
    uint32_t bReg[8];
    #pragma unroll
    for (int i = 0; i < 4; i++)
        aReg[i] = aValid[i] ? *(const float4*)(aPtr[i])
                            : make_float4(0.f, 0.f, 0.f, 0.f);
    #pragma unroll
    for (int i = 0; i < 8; i++)
        bReg[i] = g_w1h[(bK2 + 2 * i) * 128 + bN];

    for (int stage = 0; stage < 16; stage++) {
        #pragma unroll
        for (int i = 0; i < 4; i++) {
            uint32_t h0, l0, h1, l1;
            split2h(aReg[i].x, aReg[i].y, h0, l0);
            split2h(aReg[i].z, aReg[i].w, h1, l1);
            int si = (aRow + 32 * i) * A_STRIDE + aK4 * 4;
            *(uint2*)&Ahi[si] = make_uint2(h0, h1);
            *(uint2*)&Alo[si] = make_uint2(l0, l1);
        }
        #pragma unroll
        for (int i = 0; i < 8; i++) {
            int si = bN * B_STRIDE + 2 * (bK2 + 2 * i);
            *(uint32_t*)&Bh[si] = bReg[i];
        }
        __syncthreads();

        if (stage < 15) {
            int kBase = (stage + 1) * 32;
            #pragma unroll
            for (int i = 0; i < 4; i++)
                aReg[i] = aValid[i] ? *(const float4*)(aPtr[i] + kBase)
                                    : make_float4(0.f, 0.f, 0.f, 0.f);
            #pragma unroll
            for (int i = 0; i < 8; i++)
                bReg[i] = g_w1h[(kBase / 2 + bK2 + 2 * i) * 128 + bN];
        }

        #pragma unroll
        for (int ks = 0; ks < 2; ks++) {
            int kk = ks * 16;
            int aSrcRow = (g4 & 1) * 8 + r8;
            int aSrcCol = kk + (g4 >> 1) * 8;
            uint32_t ah[2][4], al[2][4];
            #pragma unroll
            for (int mt = 0; mt < 2; mt++) {
                uint32_t off = ((warp_m * 32 + mt * 16 + aSrcRow) * A_STRIDE + aSrcCol) * 2;
                ldmx4(ah[mt], sAhi + off);
                ldmx4(al[mt], sAlo + off);
            }
            int bSrcN = (g4 >> 1) * 8 + r8;
            int bSrcK = kk + (g4 & 1) * 8;
            #pragma unroll
            for (int nt2 = 0; nt2 < 4; nt2++) {
                uint32_t b[4];
                uint32_t off = ((warp_n * 64 + nt2 * 16 + bSrcN) * B_STRIDE + bSrcK) * 2;
                ldmx4(b, sBh + off);
                #pragma unroll
                for (int mt = 0; mt < 2; mt++) {
                    mma16816h(acc[mt][2 * nt2 + 0], ah[mt], b[0], b[1]);
                    mma16816h(acc[mt][2 * nt2 + 0], al[mt], b[0], b[1]);
                    mma16816h(acc[mt][2 * nt2 + 1], ah[mt], b[2], b[3]);
                    mma16816h(acc[mt][2 * nt2 + 1], al[mt], b[2], b[3]);
                }
            }
        }
        __syncthreads();
    }

    // epilogue: pack to fp16 half2, store u32
    int g = lane >> 2, tg = lane & 3;
    #pragma unroll
    for (int mt = 0; mt < 2; mt++) {
        int r0 = mBase + warp_m * 32 + mt * 16 + g;
        int r1 = r0 + 8;
        #pragma unroll
        for (int nt = 0; nt < 8; nt++) {
            int col2 = warp_n * 32 + nt * 4 + tg;   // u32 index within row
            __half2 p0 = __floats2half2_rn(acc[mt][nt][0], acc[mt][nt][1]);
            __half2 p1 = __floats2half2_rn(acc[mt][nt][2], acc[mt][nt][3]);
            if (r0 < N_NODES) g_m1h[(size_t)r0 * 64 + col2] = *(uint32_t*)&p0;
            if (r1 < N_NODES) g_m1h[(size_t)r1 * 64 + col2] = *(uint32_t*)&p1;
        }
    }
}

// ============================================================================
// CSR binning: histogram -> exclusive scan -> placement
// ============================================================================
__global__ __launch_bounds__(256) void bin_count(const int* __restrict__ ei) {
    int e = blockIdx.x * 256 + threadIdx.x;
    if (e < E_EDGES) atomicAdd(&g_deg[ei[E_EDGES + e]], 1);
}

__global__ __launch_bounds__(256) void scanA() {
    __shared__ int wsum[8];
    int t = threadIdx.x;
    int base = blockIdx.x * 1024 + t * 4;
    int v[4];
    #pragma unroll
    for (int i = 0; i < 4; i++)
        v[i] = (base + i < N_NODES) ? g_deg[base + i] : 0;
    int s = v[0] + v[1] + v[2] + v[3];
    int lane = t & 31, w = t >> 5;
    int inc = s;
    #pragma unroll
    for (int o = 1; o < 32; o <<= 1) {
        int n = __shfl_up_sync(0xFFFFFFFFu, inc, o);
        if (lane >= o) inc += n;
    }
    if (lane == 31) wsum[w] = inc;
    __syncthreads();
    if (t == 0) {
        int run = 0;
        #pragma unroll
        for (int i = 0; i < 8; i++) { int x = wsum[i]; wsum[i] = run; run += x; }
        g_bsum[blockIdx.x] = run;
    }
    __syncthreads();
    int excl = inc - s + wsum[w];
    int o0 = excl, o1 = o0 + v[0], o2 = o1 + v[1], o3 = o2 + v[2];
    if (base + 0 < N_NODES) g_off[base + 0] = o0;
    if (base + 1 < N_NODES) g_off[base + 1] = o1;
    if (base + 2 < N_NODES) g_off[base + 2] = o2;
    if (base + 3 < N_NODES) g_off[base + 3] = o3;
}

__global__ __launch_bounds__(128) void scanB(int nb) {
    __shared__ int ws[4];
    int t = threadIdx.x;
    int v = (t < nb) ? g_bsum[t] : 0;
    int lane = t & 31, w = t >> 5;
    int inc = v;
    #pragma unroll
    for (int o = 1; o < 32; o <<= 1) {
        int n = __shfl_up_sync(0xFFFFFFFFu, inc, o);
        if (lane >= o) inc += n;
    }
    if (lane == 31) ws[w] = inc;
    __syncthreads();
    if (t == 0) {
        int run = 0;
        #pragma unroll
        for (int i = 0; i < 4; i++) { int x = ws[i]; ws[i] = run; run += x; }
    }
    __syncthreads();
    if (t < nb) g_bscan[t] = inc - v + ws[w];
}

__global__ __launch_bounds__(256) void scanC() {
    int add = g_bscan[blockIdx.x];
    int base = blockIdx.x * 1024 + threadIdx.x;
    #pragma unroll
    for (int i = 0; i < 4; i++) {
        int idx = base + i * 256;
        if (idx < N_NODES) {
            int val = g_off[idx] + add;
            g_off[idx] = val;
            g_cur[idx] = val;
        }
    }
}

__global__ __launch_bounds__(256) void bin_fill(const int* __restrict__ ei,
                                                const float* __restrict__ ew) {
    int e = blockIdx.x * 256 + threadIdx.x;
    if (e >= E_EDGES) return;
    int src = ei[e];
    int dst = ei[E_EDGES + e];
    int pos = atomicAdd(&g_cur[dst], 1);
    g_esrc[pos] = src;
    g_ewp[pos] = ew[e];
}

// ============================================================================
// Agg1 (dst-driven, fused b1+relu), fp16 m1 gather, 4-deep unroll
// ============================================================================
__global__ __launch_bounds__(256) void agg1_kernel(const float* __restrict__ b1) {
    int wv = blockIdx.x * 8 + (threadIdx.x >> 5);
    int lane = threadIdx.x & 31;
    if (wv >= N_NODES) return;
    int beg = g_off[wv];
    int end = (wv == N_NODES - 1) ? E_EDGES : g_off[wv + 1];

    float4 a0 = make_float4(0.f, 0.f, 0.f, 0.f);
    float4 a1 = make_float4(0.f, 0.f, 0.f, 0.f);
    float4 a2 = make_float4(0.f, 0.f, 0.f, 0.f);
    float4 a3 = make_float4(0.f, 0.f, 0.f, 0.f);
    int j = beg;
    for (; j + 4 <= end; j += 4) {
        int s0 = g_esrc[j], s1 = g_esrc[j + 1], s2 = g_esrc[j + 2], s3 = g_esrc[j + 3];
        float w0 = g_ewp[j], w1 = g_ewp[j + 1], w2 = g_ewp[j + 2], w3 = g_ewp[j + 3];
        uint2 q0 = ((const uint2*)(g_m1h + (size_t)s0 * 64))[lane];
        uint2 q1 = ((const uint2*)(g_m1h + (size_t)s1 * 64))[lane];
        uint2 q2 = ((const uint2*)(g_m1h + (size_t)s2 * 64))[lane];
        uint2 q3 = ((const uint2*)(g_m1h + (size_t)s3 * 64))[lane];
        float2 u, v;
        u = __half22float2(*(__half2*)&q0.x); v = __half22float2(*(__half2*)&q0.y);
        a0.x += u.x * w0; a0.y += u.y * w0; a0.z += v.x * w0; a0.w += v.y * w0;
        u = __half22float2(*(__half2*)&q1.x); v = __half22float2(*(__half2*)&q1.y);
        a1.x += u.x * w1; a1.y += u.y * w1; a1.z += v.x * w1; a1.w += v.y * w1;
        u = __half22float2(*(__half2*)&q2.x); v = __half22float2(*(__half2*)&q2.y);
        a2.x += u.x * w2; a2.y += u.y * w2; a2.z += v.x * w2; a2.w += v.y * w2;
        u = __half22float2(*(__half2*)&q3.x); v = __half22float2(*(__half2*)&q3.y);
        a3.x += u.x * w3; a3.y += u.y * w3; a3.z += v.x * w3; a3.w += v.y * w3;
    }
    for (; j < end; j++) {
        int s0 = g_esrc[j];
        float w0 = g_ewp[j];
        uint2 q0 = ((const uint2*)(g_m1h + (size_t)s0 * 64))[lane];
        float2 u = __half22float2(*(__half2*)&q0.x);
        float2 v = __half22float2(*(__half2*)&q0.y);
        a0.x += u.x * w0; a0.y += u.y * w0; a0.z += v.x * w0; a0.w += v.y * w0;
    }
    float4 bb = ((const float4*)b1)[lane];
    float4 r;
    r.x = fmaxf(a0.x + a1.x + a2.x + a3.x + bb.x, 0.f);
    r.y = fmaxf(a0.y + a1.y + a2.y + a3.y + bb.y, 0.f);
    r.z = fmaxf(a0.z + a1.z + a2.z + a3.z + bb.z, 0.f);
    r.w = fmaxf(a0.w + a1.w + a2.w + a3.w + bb.w, 0.f);
    ((float4*)(g_agg1 + (size_t)wv * F_HID))[lane] = r;
}

// ============================================================================
// GEMM2 (mma fp16 2-term A): m2h[N,40] = agg1 @ W2[128,40], fp16 output
// ============================================================================
#define G2K 136   // smem row stride in shorts (272B: 8-row groups conflict-free)
#define G2M_SMEM ((2 * 128 * G2K + 40 * G2K) * 2)

__global__ __launch_bounds__(256) void gemm2_mma() {
    extern __shared__ unsigned short g2sm[];
    unsigned short* Ahi = g2sm;                    // [128][G2K]
    unsigned short* Alo = g2sm + 128 * G2K;
    uint32_t* Bh32 = (uint32_t*)(g2sm + 2 * 128 * G2K);   // [40][G2K/2]

    int tid = threadIdx.x, wid = tid >> 5, lane = tid & 31;
    int rowBase = blockIdx.x * 128;

    #pragma unroll
    for (int i = 0; i < 10; i++) {
        int idx = tid + 256 * i;
        int n = idx >> 6, k2 = idx & 63;
        Bh32[n * (G2K / 2) + k2] = g_w2h[idx];
    }
    #pragma unroll
    for (int i = 0; i < 16; i++) {
        int idx = tid + 256 * i;            // 4096 float4s
        int r = idx >> 5, k4 = idx & 31;
        int row = rowBase + r;
        float4 v = make_float4(0.f, 0.f, 0.f, 0.f);
        if (row < N_NODES)
            v = ((const float4*)(g_agg1 + (size_t)row * F_HID))[k4];
        uint32_t h0, l0, h1, l1;
        split2h(v.x, v.y, h0, l0);
        split2h(v.z, v.w, h1, l1);
        int si = r * G2K + k4 * 4;
        *(uint2*)&Ahi[si] = make_uint2(h0, h1);
        *(uint2*)&Alo[si] = make_uint2(l0, l1);
    }
    __syncthreads();

    uint32_t sbase = (uint32_t)__cvta_generic_to_shared(g2sm);
    uint32_t sAhi = sbase;
    uint32_t sAlo = sbase + 128 * G2K * 2;
    uint32_t sBh  = sbase + 2 * 128 * G2K * 2;

    float acc[5][4];
    #pragma unroll
    for (int nt = 0; nt < 5; nt++)
        #pragma unroll
        for (int i = 0; i < 4; i++) acc[nt][i] = 0.f;

    int g4 = lane >> 3, r8 = lane & 7;
    int aSrcRow = (g4 & 1) * 8 + r8;
    int aColSel = (g4 >> 1) * 8;
    int bSrcN = (g4 >> 1) * 8 + r8;
    int bKSel = (g4 & 1) * 8;
    int b2N = lane & 7, b2KSel = ((lane >> 3) & 1) * 8;

    #pragma unroll
    for (int ks = 0; ks < 8; ks++) {
        int kk = ks * 16;
        uint32_t ah[4], al[4];
        uint32_t aoff = ((wid * 16 + aSrcRow) * G2K + kk + aColSel) * 2;
        ldmx4(ah, sAhi + aoff);
        ldmx4(al, sAlo + aoff);
        uint32_t b[4];
        uint32_t boff = ((bSrcN) * G2K + kk + bKSel) * 2;
        ldmx4(b, sBh + boff);
        mma16816h(acc[0], ah, b[0], b[1]);
        mma16816h(acc[0], al, b[0], b[1]);
        mma16816h(acc[1], ah, b[2], b[3]);
        mma16816h(acc[1], al, b[2], b[3]);
        boff = ((16 + bSrcN) * G2K + kk + bKSel) * 2;
        ldmx4(b, sBh + boff);
        mma16816h(acc[2], ah, b[0], b[1]);
        mma16816h(acc[2], al, b[0], b[1]);
        mma16816h(acc[3], ah, b[2], b[3]);
        mma16816h(acc[3], al, b[2], b[3]);
        uint32_t b2[2];
        uint32_t boff2 = ((32 + b2N) * G2K + kk + b2KSel) * 2;
        ldmx2(b2, sBh + boff2);
        mma16816h(acc[4], ah, b2[0], b2[1]);
        mma16816h(acc[4], al, b2[0], b2[1]);
    }

    int g = lane >> 2, tg = lane & 3;
    int r0 = rowBase + wid * 16 + g, r1 = r0 + 8;
    #pragma unroll
    for (int nt = 0; nt < 5; nt++) {
        int col2 = nt * 4 + tg;   // u32 index within 20-u32 row
        __half2 p0 = __floats2half2_rn(acc[nt][0], acc[nt][1]);
        __half2 p1 = __floats2half2_rn(acc[nt][2], acc[nt][3]);
        if (r0 < N_NODES) g_m2h[(size_t)r0 * 20 + col2] = *(uint32_t*)&p0;
        if (r1 < N_NODES) g_m2h[(size_t)r1 * 20 + col2] = *(uint32_t*)&p1;
    }
}

// ============================================================================
// Agg2 + b2 + log_softmax fused (dst-driven), fp16 m2 gather, 4-deep unroll
// ============================================================================
__global__ __launch_bounds__(256) void agg2_ls_kernel(const float* __restrict__ b2,
                                                      float* __restrict__ out) {
    int wv = blockIdx.x * 8 + (threadIdx.x >> 5);
    int lane = threadIdx.x & 31;
    if (wv >= N_NODES) return;
    int beg = g_off[wv];
    int end = (wv == N_NODES - 1) ? E_EDGES : g_off[wv + 1];
    bool act = lane < 10;

    float4 a0 = make_float4(0.f, 0.f, 0.f, 0.f);
    float4 a1 = make_float4(0.f, 0.f, 0.f, 0.f);
    float4 a2 = make_float4(0.f, 0.f, 0.f, 0.f);
    float4 a3 = make_float4(0.f, 0.f, 0.f, 0.f);
    int j = beg;
    for (; j + 4 <= end; j += 4) {
        int s0 = g_esrc[j], s1 = g_esrc[j + 1], s2 = g_esrc[j + 2], s3 = g_esrc[j + 3];
        float w0 = g_ewp[j], w1 = g_ewp[j + 1], w2 = g_ewp[j + 2], w3 = g_ewp[j + 3];
        if (act) {
            uint2 q0 = ((const uint2*)(g_m2h + (size_t)s0 * 20))[lane];
            uint2 q1 = ((const uint2*)(g_m2h + (size_t)s1 * 20))[lane];
            uint2 q2 = ((const uint2*)(g_m2h + (size_t)s2 * 20))[lane];
            uint2 q3 = ((const uint2*)(g_m2h + (size_t)s3 * 20))[lane];
            float2 u, v;
            u = __half22float2(*(__half2*)&q0.x); v = __half22float2(*(__half2*)&q0.y);
            a0.x += u.x * w0; a0.y += u.y * w0; a0.z += v.x * w0; a0.w += v.y * w0;
            u = __half22float2(*(__half2*)&q1.x); v = __half22float2(*(__half2*)&q1.y);
            a1.x += u.x * w1; a1.y += u.y * w1; a1.z += v.x * w1; a1.w += v.y * w1;
            u = __half22float2(*(__half2*)&q2.x); v = __half22float2(*(__half2*)&q2.y);
            a2.x += u.x * w2; a2.y += u.y * w2; a2.z += v.x * w2; a2.w += v.y * w2;
            u = __half22float2(*(__half2*)&q3.x); v = __half22float2(*(__half2*)&q3.y);
            a3.x += u.x * w3; a3.y += u.y * w3; a3.z += v.x * w3; a3.w += v.y * w3;
        }
    }
    for (; j < end; j++) {
        int s0 = g_esrc[j];
        float w0 = g_ewp[j];
        if (act) {
            uint2 q0 = ((const uint2*)(g_m2h + (size_t)s0 * 20))[lane];
            float2 u = __half22float2(*(__half2*)&q0.x);
            float2 v = __half22float2(*(__half2*)&q0.y);
            a0.x += u.x * w0; a0.y += u.y * w0; a0.z += v.x * w0; a0.w += v.y * w0;
        }
    }
    float4 x = make_float4(a0.x + a1.x + a2.x + a3.x, a0.y + a1.y + a2.y + a3.y,
                           a0.z + a1.z + a2.z + a3.z, a0.w + a1.w + a2.w + a3.w);
    if (act) {
        float4 bb = ((const float4*)b2)[lane];
        x.x += bb.x; x.y += bb.y; x.z += bb.z; x.w += bb.w;
    }

    float m = act ? fmaxf(fmaxf(x.x, x.y), fmaxf(x.z, x.w)) : -1e30f;
    #pragma unroll
    for (int o = 16; o; o >>= 1) m = fmaxf(m, __shfl_xor_sync(0xFFFFFFFFu, m, o));

    float s = act ? (__expf(x.x - m) + __expf(x.y - m) +
                     __expf(x.z - m) + __expf(x.w - m)) : 0.f;
    #pragma unroll
    for (int o = 16; o; o >>= 1) s += __shfl_xor_sync(0xFFFFFFFFu, s, o);

    float lse = m + __logf(s);
    if (act) {
        x.x -= lse; x.y -= lse; x.z -= lse; x.w -= lse;
        ((float4*)(out + (size_t)wv * F_OUT))[lane] = x;
    }
}

// ============================================================================
extern "C" void kernel_launch(void* const* d_in, const int* in_sizes, int n_in,
                              void* d_out, int out_size) {
    const float* X   = (const float*)d_in[0];        // [100000,512]
    const int*   EI  = (const int*)d_in[1];          // [2,1600000] int32
    const float* EW  = (const float*)d_in[2];        // [1600000]
    const float* W1  = (const float*)d_in[3];        // [512,128]
    const float* B1  = (const float*)d_in[4];        // [128]
    const float* W2  = (const float*)d_in[5];        // [128,40]
    const float* B2  = (const float*)d_in[6];        // [40]
    float*       OUT = (float*)d_out;                // [100000,40]

    // one-time setup (first call is outside graph capture)
    static cudaStream_t s2 = nullptr;
    static cudaEvent_t evFork = nullptr, evJoin = nullptr;
    if (!s2) {
        cudaStreamCreateWithFlags(&s2, cudaStreamNonBlocking);
        cudaEventCreateWithFlags(&evFork, cudaEventDisableTiming);
        cudaEventCreateWithFlags(&evJoin, cudaEventDisableTiming);
        cudaFuncSetAttribute(gemm2_mma,
                             cudaFuncAttributeMaxDynamicSharedMemorySize, G2M_SMEM);
    }

    const int NB_SCAN = (N_NODES + 1023) / 1024;     // 98
    const int EB = E_EDGES / 256;                    // 6250 (exact)

    void* degPtr = nullptr;
    cudaGetSymbolAddress(&degPtr, g_deg);

    // ---- fork: CSR binning on s2, overlapped with gemm1 on stream 0 ----
    cudaEventRecord(evFork, 0);
    cudaStreamWaitEvent(s2, evFork, 0);

    cudaMemsetAsync(degPtr, 0, N_NODES * sizeof(int), s2);
    bin_count<<<EB, 256, 0, s2>>>(EI);
    scanA<<<NB_SCAN, 256, 0, s2>>>();
    scanB<<<1, 128, 0, s2>>>(NB_SCAN);
    scanC<<<NB_SCAN, 256, 0, s2>>>();
    bin_fill<<<EB, 256, 0, s2>>>(EI, EW);
    cudaEventRecord(evJoin, s2);

    // stream 0: weight prep + GEMM1 (independent of binning)
    prep_w1<<<128, 256>>>(W1);
    prep_w2<<<10, 256>>>(W2);
    gemm1_mma<<<(N_NODES + 127) / 128, 256>>>(X);

    // ---- join ----
    cudaStreamWaitEvent(0, evJoin, 0);

    // Agg1 (fused b1 + relu): agg1 = relu(S(m1) + b1)
    agg1_kernel<<<(N_NODES + 7) / 8, 256>>>(B1);

    // GEMM2 (tensor): m2 = agg1 @ W2, fp16 out
    gemm2_mma<<<(N_NODES + 127) / 128, 256, G2M_SMEM>>>();

    // Agg2 + b2 + log_softmax fused, writes d_out
    agg2_ls_kernel<<<(N_NODES + 7) / 8, 256>>>(B2, OUT);
}

// round 17
// speedup vs baseline: 1.4346x; 1.1885x over previous
#include <cuda_runtime.h>
#include <cuda_fp16.h>
#include <cstdint>

#define N_NODES 100000
#define E_EDGES 1600000
#define F_IN    512
#define F_HID   128
#define F_OUT   40

// Scratch (allocation-free rule: __device__ globals)
__device__ uint32_t g_m1h[(size_t)N_NODES * 64];   // X@W1 as half2-packed fp16
__device__ float g_agg1[(size_t)N_NODES * F_HID];  // relu(scatter-sum + b1), fp32
__device__ uint32_t g_m2h[(size_t)N_NODES * 20];   // h@W2 as half2-packed fp16

// W1 fp16, pair-packed: [k2][n] uint32 = (fp16(W[2k2][n]), fp16(W[2k2+1][n]))
__device__ uint32_t g_w1h[256 * 128];
// W2 fp16, [n][k2] pair-packed
__device__ uint32_t g_w2h[40 * 64];

// CSR binning scratch (rebuilt every launch)
__device__ int   g_deg[N_NODES];
__device__ int   g_off[N_NODES];
__device__ int   g_cur[N_NODES];
__device__ int   g_bsum[128];
__device__ int   g_bscan[128];
__device__ int   g_esrc[E_EDGES];
__device__ float g_ewp[E_EDGES];

// ============================================================================
// helpers
// ============================================================================
__device__ __forceinline__ void mma16816h(float* d, const uint32_t* a,
                                          uint32_t b0, uint32_t b1) {
    asm volatile(
        "mma.sync.aligned.m16n8k16.row.col.f32.f16.f16.f32 "
        "{%0,%1,%2,%3}, {%4,%5,%6,%7}, {%8,%9}, {%0,%1,%2,%3};"
        : "+f"(d[0]), "+f"(d[1]), "+f"(d[2]), "+f"(d[3])
        : "r"(a[0]), "r"(a[1]), "r"(a[2]), "r"(a[3]), "r"(b0), "r"(b1));
}

__device__ __forceinline__ void ldmx4(uint32_t* r, uint32_t addr) {
    asm volatile(
        "ldmatrix.sync.aligned.m8n8.x4.shared.b16 {%0,%1,%2,%3}, [%4];"
        : "=r"(r[0]), "=r"(r[1]), "=r"(r[2]), "=r"(r[3]) : "r"(addr));
}
__device__ __forceinline__ void ldmx2(uint32_t* r, uint32_t addr) {
    asm volatile(
        "ldmatrix.sync.aligned.m8n8.x2.shared.b16 {%0,%1}, [%2];"
        : "=r"(r[0]), "=r"(r[1]) : "r"(addr));
}

// fp16 hi/lo split of a pair of floats (packed half2 as uint32)
__device__ __forceinline__ void split2h(float x, float y,
                                        uint32_t& hi, uint32_t& lo) {
    __half2 h = __floats2half2_rn(x, y);
    float hx = __half2float(__low2half(h)), hy = __half2float(__high2half(h));
    __half2 l = __floats2half2_rn(x - hx, y - hy);
    hi = *(uint32_t*)&h;
    lo = *(uint32_t*)&l;
}

// ============================================================================
// prep_w1 / prep_w2: one-time fp16 packing of weights
// ============================================================================
__global__ __launch_bounds__(256) void prep_w1(const float* __restrict__ W1) {
    int i = blockIdx.x * 256 + threadIdx.x;   // i = k2*128 + n
    int k2 = i >> 7, n = i & 127;
    float w0 = W1[(size_t)(2 * k2) * F_HID + n];
    float w1 = W1[(size_t)(2 * k2 + 1) * F_HID + n];
    __half2 h = __floats2half2_rn(w0, w1);
    g_w1h[i] = *(uint32_t*)&h;
}

__global__ __launch_bounds__(256) void prep_w2(const float* __restrict__ W2) {
    int i = blockIdx.x * 256 + threadIdx.x;   // i = n*64 + k2
    if (i >= 40 * 64) return;
    int n = i >> 6, k2 = i & 63;
    float w0 = W2[(size_t)(2 * k2) * F_OUT + n];
    float w1 = W2[(size_t)(2 * k2 + 1) * F_OUT + n];
    __half2 h = __floats2half2_rn(w0, w1);
    g_w2h[i] = *(uint32_t*)&h;
}

// ============================================================================
// GEMM1 (mma.sync fp16 single-term): m1h[N,128] = fp16(X)[N,512] @ fp16(W1)
// Block 128x128, BK=32, 8 warps (4m x 2n), sw-pipelined LDG, ldmatrix frags.
// Dynamic smem padded to 80KB => hard cap of 2 CTAs/SM (round-14 residency)
// to avoid the cross-CTA L1tex-queue contention observed in round 15.
// ============================================================================
#define A_STRIDE 40   // 80B rows -> ldmatrix 8-row groups hit distinct banks
#define B_STRIDE 40
#define G1_SMEM (80 * 1024)

__global__ __launch_bounds__(256) void gemm1_mma(const float* __restrict__ X) {
    extern __shared__ __align__(16) unsigned short g1sm[];
    unsigned short* Ahi = g1sm;                        // [128 * A_STRIDE]
    unsigned short* Bh  = g1sm + 128 * A_STRIDE;       // [128 * B_STRIDE]

    int tid = threadIdx.x;
    int wid = tid >> 5, lane = tid & 31;
    int warp_m = wid >> 1;
    int warp_n = wid & 1;
    int mBase = blockIdx.x * 128;

    uint32_t sAhi = (uint32_t)__cvta_generic_to_shared(Ahi);
    uint32_t sBh  = (uint32_t)__cvta_generic_to_shared(Bh);

    int aRow = tid >> 3, aK4 = tid & 7;
    bool aValid[4];
    const float* aPtr[4];
    #pragma unroll
    for (int i = 0; i < 4; i++) {
        int row = aRow + 32 * i;
        int grow = mBase + row;
        aValid[i] = grow < N_NODES;
        aPtr[i] = X + (size_t)(aValid[i] ? grow : 0) * F_IN + aK4 * 4;
    }
    int bN = tid & 127, bK2 = tid >> 7;
    int g4 = lane >> 3, r8 = lane & 7;

    float acc[2][8][4];
    #pragma unroll
    for (int mt = 0; mt < 2; mt++)
        #pragma unroll
        for (int nt = 0; nt < 8; nt++)
            #pragma unroll
            for (int i = 0; i < 4; i++) acc[mt][nt][i] = 0.f;

    float4 aReg[4];
    uint32_t bReg[8];
    #pragma unroll
    for (int i = 0; i < 4; i++)
        aReg[i] = aValid[i] ? *(const float4*)(aPtr[i])
                            : make_float4(0.f, 0.f, 0.f, 0.f);
    #pragma unroll
    for (int i = 0; i < 8; i++)
        bReg[i] = g_w1h[(bK2 + 2 * i) * 128 + bN];

    for (int stage = 0; stage < 16; stage++) {
        #pragma unroll
        for (int i = 0; i < 4; i++) {
            __half2 h0 = __floats2half2_rn(aReg[i].x, aReg[i].y);
            __half2 h1 = __floats2half2_rn(aReg[i].z, aReg[i].w);
            int si = (aRow + 32 * i) * A_STRIDE + aK4 * 4;
            *(uint2*)&Ahi[si] = make_uint2(*(uint32_t*)&h0, *(uint32_t*)&h1);
        }
        #pragma unroll
        for (int i = 0; i < 8; i++) {
            int si = bN * B_STRIDE + 2 * (bK2 + 2 * i);
            *(uint32_t*)&Bh[si] = bReg[i];
        }
        __syncthreads();

        if (stage < 15) {
            int kBase = (stage + 1) * 32;
            #pragma unroll
            for (int i = 0; i < 4; i++)
                aReg[i] = aValid[i] ? *(const float4*)(aPtr[i] + kBase)
                                    : make_float4(0.f, 0.f, 0.f, 0.f);
            #pragma unroll
            for (int i = 0; i < 8; i++)
                bReg[i] = g_w1h[(kBase / 2 + bK2 + 2 * i) * 128 + bN];
        }

        #pragma unroll
        for (int ks = 0; ks < 2; ks++) {
            int kk = ks * 16;
            int aSrcRow = (g4 & 1) * 8 + r8;
            int aSrcCol = kk + (g4 >> 1) * 8;
            uint32_t ah[2][4];
            #pragma unroll
            for (int mt = 0; mt < 2; mt++) {
                uint32_t off = ((warp_m * 32 + mt * 16 + aSrcRow) * A_STRIDE + aSrcCol) * 2;
                ldmx4(ah[mt], sAhi + off);
            }
            int bSrcN = (g4 >> 1) * 8 + r8;
            int bSrcK = kk + (g4 & 1) * 8;
            #pragma unroll
            for (int nt2 = 0; nt2 < 4; nt2++) {
                uint32_t b[4];
                uint32_t off = ((warp_n * 64 + nt2 * 16 + bSrcN) * B_STRIDE + bSrcK) * 2;
                ldmx4(b, sBh + off);
                #pragma unroll
                for (int mt = 0; mt < 2; mt++) {
                    mma16816h(acc[mt][2 * nt2 + 0], ah[mt], b[0], b[1]);
                    mma16816h(acc[mt][2 * nt2 + 1], ah[mt], b[2], b[3]);
                }
            }
        }
        __syncthreads();
    }

    // epilogue: pack to fp16 half2, store u32
    int g = lane >> 2, tg = lane & 3;
    #pragma unroll
    for (int mt = 0; mt < 2; mt++) {
        int r0 = mBase + warp_m * 32 + mt * 16 + g;
        int r1 = r0 + 8;
        #pragma unroll
        for (int nt = 0; nt < 8; nt++) {
            int col2 = warp_n * 32 + nt * 4 + tg;   // u32 index within row
            __half2 p0 = __floats2half2_rn(acc[mt][nt][0], acc[mt][nt][1]);
            __half2 p1 = __floats2half2_rn(acc[mt][nt][2], acc[mt][nt][3]);
            if (r0 < N_NODES) g_m1h[(size_t)r0 * 64 + col2] = *(uint32_t*)&p0;
            if (r1 < N_NODES) g_m1h[(size_t)r1 * 64 + col2] = *(uint32_t*)&p1;
        }
    }
}

// ============================================================================
// CSR binning: histogram -> exclusive scan -> placement
// ============================================================================
__global__ __launch_bounds__(256) void bin_count(const int* __restrict__ ei) {
    int e = blockIdx.x * 256 + threadIdx.x;
    if (e < E_EDGES) atomicAdd(&g_deg[ei[E_EDGES + e]], 1);
}

__global__ __launch_bounds__(256) void scanA() {
    __shared__ int wsum[8];
    int t = threadIdx.x;
    int base = blockIdx.x * 1024 + t * 4;
    int v[4];
    #pragma unroll
    for (int i = 0; i < 4; i++)
        v[i] = (base + i < N_NODES) ? g_deg[base + i] : 0;
    int s = v[0] + v[1] + v[2] + v[3];
    int lane = t & 31, w = t >> 5;
    int inc = s;
    #pragma unroll
    for (int o = 1; o < 32; o <<= 1) {
        int n = __shfl_up_sync(0xFFFFFFFFu, inc, o);
        if (lane >= o) inc += n;
    }
    if (lane == 31) wsum[w] = inc;
    __syncthreads();
    if (t == 0) {
        int run = 0;
        #pragma unroll
        for (int i = 0; i < 8; i++) { int x = wsum[i]; wsum[i] = run; run += x; }
        g_bsum[blockIdx.x] = run;
    }
    __syncthreads();
    int excl = inc - s + wsum[w];
    int o0 = excl, o1 = o0 + v[0], o2 = o1 + v[1], o3 = o2 + v[2];
    if (base + 0 < N_NODES) g_off[base + 0] = o0;
    if (base + 1 < N_NODES) g_off[base + 1] = o1;
    if (base + 2 < N_NODES) g_off[base + 2] = o2;
    if (base + 3 < N_NODES) g_off[base + 3] = o3;
}

__global__ __launch_bounds__(128) void scanB(int nb) {
    __shared__ int ws[4];
    int t = threadIdx.x;
    int v = (t < nb) ? g_bsum[t] : 0;
    int lane = t & 31, w = t >> 5;
    int inc = v;
    #pragma unroll
    for (int o = 1; o < 32; o <<= 1) {
        int n = __shfl_up_sync(0xFFFFFFFFu, inc, o);
        if (lane >= o) inc += n;
    }
    if (lane == 31) ws[w] = inc;
    __syncthreads();
    if (t == 0) {
        int run = 0;
        #pragma unroll
        for (int i = 0; i < 4; i++) { int x = ws[i]; ws[i] = run; run += x; }
    }
    __syncthreads();
    if (t < nb) g_bscan[t] = inc - v + ws[w];
}

__global__ __launch_bounds__(256) void scanC() {
    int add = g_bscan[blockIdx.x];
    int base = blockIdx.x * 1024 + threadIdx.x;
    #pragma unroll
    for (int i = 0; i < 4; i++) {
        int idx = base + i * 256;
        if (idx < N_NODES) {
            int val = g_off[idx] + add;
            g_off[idx] = val;
            g_cur[idx] = val;
        }
    }
}

__global__ __launch_bounds__(256) void bin_fill(const int* __restrict__ ei,
                                                const float* __restrict__ ew) {
    int e = blockIdx.x * 256 + threadIdx.x;
    if (e >= E_EDGES) return;
    int src = ei[e];
    int dst = ei[E_EDGES + e];
    int pos = atomicAdd(&g_cur[dst], 1);
    g_esrc[pos] = src;
    g_ewp[pos] = ew[e];
}

// ============================================================================
// Agg1 (dst-driven, fused b1+relu), fp16 m1 gather, 4-deep unroll
// ============================================================================
__global__ __launch_bounds__(256) void agg1_kernel(const float* __restrict__ b1) {
    int wv = blockIdx.x * 8 + (threadIdx.x >> 5);
    int lane = threadIdx.x & 31;
    if (wv >= N_NODES) return;
    int beg = g_off[wv];
    int end = (wv == N_NODES - 1) ? E_EDGES : g_off[wv + 1];

    float4 a0 = make_float4(0.f, 0.f, 0.f, 0.f);
    float4 a1 = make_float4(0.f, 0.f, 0.f, 0.f);
    float4 a2 = make_float4(0.f, 0.f, 0.f, 0.f);
    float4 a3 = make_float4(0.f, 0.f, 0.f, 0.f);
    int j = beg;
    for (; j + 4 <= end; j += 4) {
        int s0 = g_esrc[j], s1 = g_esrc[j + 1], s2 = g_esrc[j + 2], s3 = g_esrc[j + 3];
        float w0 = g_ewp[j], w1 = g_ewp[j + 1], w2 = g_ewp[j + 2], w3 = g_ewp[j + 3];
        uint2 q0 = ((const uint2*)(g_m1h + (size_t)s0 * 64))[lane];
        uint2 q1 = ((const uint2*)(g_m1h + (size_t)s1 * 64))[lane];
        uint2 q2 = ((const uint2*)(g_m1h + (size_t)s2 * 64))[lane];
        uint2 q3 = ((const uint2*)(g_m1h + (size_t)s3 * 64))[lane];
        float2 u, v;
        u = __half22float2(*(__half2*)&q0.x); v = __half22float2(*(__half2*)&q0.y);
        a0.x += u.x * w0; a0.y += u.y * w0; a0.z += v.x * w0; a0.w += v.y * w0;
        u = __half22float2(*(__half2*)&q1.x); v = __half22float2(*(__half2*)&q1.y);
        a1.x += u.x * w1; a1.y += u.y * w1; a1.z += v.x * w1; a1.w += v.y * w1;
        u = __half22float2(*(__half2*)&q2.x); v = __half22float2(*(__half2*)&q2.y);
        a2.x += u.x * w2; a2.y += u.y * w2; a2.z += v.x * w2; a2.w += v.y * w2;
        u = __half22float2(*(__half2*)&q3.x); v = __half22float2(*(__half2*)&q3.y);
        a3.x += u.x * w3; a3.y += u.y * w3; a3.z += v.x * w3; a3.w += v.y * w3;
    }
    for (; j < end; j++) {
        int s0 = g_esrc[j];
        float w0 = g_ewp[j];
        uint2 q0 = ((const uint2*)(g_m1h + (size_t)s0 * 64))[lane];
        float2 u = __half22float2(*(__half2*)&q0.x);
        float2 v = __half22float2(*(__half2*)&q0.y);
        a0.x += u.x * w0; a0.y += u.y * w0; a0.z += v.x * w0; a0.w += v.y * w0;
    }
    float4 bb = ((const float4*)b1)[lane];
    float4 r;
    r.x = fmaxf(a0.x + a1.x + a2.x + a3.x + bb.x, 0.f);
    r.y = fmaxf(a0.y + a1.y + a2.y + a3.y + bb.y, 0.f);
    r.z = fmaxf(a0.z + a1.z + a2.z + a3.z + bb.z, 0.f);
    r.w = fmaxf(a0.w + a1.w + a2.w + a3.w + bb.w, 0.f);
    ((float4*)(g_agg1 + (size_t)wv * F_HID))[lane] = r;
}

// ============================================================================
// GEMM2 (mma fp16 2-term A): m2h[N,40] = agg1 @ W2[128,40], fp16 output
// ============================================================================
#define G2K 136   // smem row stride in shorts (272B: 8-row groups conflict-free)
#define G2M_SMEM ((2 * 128 * G2K + 40 * G2K) * 2)

__global__ __launch_bounds__(256) void gemm2_mma() {
    extern __shared__ unsigned short g2sm[];
    unsigned short* Ahi = g2sm;                    // [128][G2K]
    unsigned short* Alo = g2sm + 128 * G2K;
    uint32_t* Bh32 = (uint32_t*)(g2sm + 2 * 128 * G2K);   // [40][G2K/2]

    int tid = threadIdx.x, wid = tid >> 5, lane = tid & 31;
    int rowBase = blockIdx.x * 128;

    #pragma unroll
    for (int i = 0; i < 10; i++) {
        int idx = tid + 256 * i;
        int n = idx >> 6, k2 = idx & 63;
        Bh32[n * (G2K / 2) + k2] = g_w2h[idx];
    }
    #pragma unroll
    for (int i = 0; i < 16; i++) {
        int idx = tid + 256 * i;            // 4096 float4s
        int r = idx >> 5, k4 = idx & 31;
        int row = rowBase + r;
        float4 v = make_float4(0.f, 0.f, 0.f, 0.f);
        if (row < N_NODES)
            v = ((const float4*)(g_agg1 + (size_t)row * F_HID))[k4];
        uint32_t h0, l0, h1, l1;
        split2h(v.x, v.y, h0, l0);
        split2h(v.z, v.w, h1, l1);
        int si = r * G2K + k4 * 4;
        *(uint2*)&Ahi[si] = make_uint2(h0, h1);
        *(uint2*)&Alo[si] = make_uint2(l0, l1);
    }
    __syncthreads();

    uint32_t sbase = (uint32_t)__cvta_generic_to_shared(g2sm);
    uint32_t sAhi = sbase;
    uint32_t sAlo = sbase + 128 * G2K * 2;
    uint32_t sBh  = sbase + 2 * 128 * G2K * 2;

    float acc[5][4];
    #pragma unroll
    for (int nt = 0; nt < 5; nt++)
        #pragma unroll
        for (int i = 0; i < 4; i++) acc[nt][i] = 0.f;

    int g4 = lane >> 3, r8 = lane & 7;
    int aSrcRow = (g4 & 1) * 8 + r8;
    int aColSel = (g4 >> 1) * 8;
    int bSrcN = (g4 >> 1) * 8 + r8;
    int bKSel = (g4 & 1) * 8;
    int b2N = lane & 7, b2KSel = ((lane >> 3) & 1) * 8;

    #pragma unroll
    for (int ks = 0; ks < 8; ks++) {
        int kk = ks * 16;
        uint32_t ah[4], al[4];
        uint32_t aoff = ((wid * 16 + aSrcRow) * G2K + kk + aColSel) * 2;
        ldmx4(ah, sAhi + aoff);
        ldmx4(al, sAlo + aoff);
        uint32_t b[4];
        uint32_t boff = ((bSrcN) * G2K + kk + bKSel) * 2;
        ldmx4(b, sBh + boff);
        mma16816h(acc[0], ah, b[0], b[1]);
        mma16816h(acc[0], al, b[0], b[1]);
        mma16816h(acc[1], ah, b[2], b[3]);
        mma16816h(acc[1], al, b[2], b[3]);
        boff = ((16 + bSrcN) * G2K + kk + bKSel) * 2;
        ldmx4(b, sBh + boff);
        mma16816h(acc[2], ah, b[0], b[1]);
        mma16816h(acc[2], al, b[0], b[1]);
        mma16816h(acc[3], ah, b[2], b[3]);
        mma16816h(acc[3], al, b[2], b[3]);
        uint32_t b2[2];
        uint32_t boff2 = ((32 + b2N) * G2K + kk + b2KSel) * 2;
        ldmx2(b2, sBh + boff2);
        mma16816h(acc[4], ah, b2[0], b2[1]);
        mma16816h(acc[4], al, b2[0], b2[1]);
    }

    int g = lane >> 2, tg = lane & 3;
    int r0 = rowBase + wid * 16 + g, r1 = r0 + 8;
    #pragma unroll
    for (int nt = 0; nt < 5; nt++) {
        int col2 = nt * 4 + tg;   // u32 index within 20-u32 row
        __half2 p0 = __floats2half2_rn(acc[nt][0], acc[nt][1]);
        __half2 p1 = __floats2half2_rn(acc[nt][2], acc[nt][3]);
        if (r0 < N_NODES) g_m2h[(size_t)r0 * 20 + col2] = *(uint32_t*)&p0;
        if (r1 < N_NODES) g_m2h[(size_t)r1 * 20 + col2] = *(uint32_t*)&p1;
    }
}

// ============================================================================
// Agg2 + b2 + log_softmax fused (dst-driven), fp16 m2 gather, 4-deep unroll
// ============================================================================
__global__ __launch_bounds__(256) void agg2_ls_kernel(const float* __restrict__ b2,
                                                      float* __restrict__ out) {
    int wv = blockIdx.x * 8 + (threadIdx.x >> 5);
    int lane = threadIdx.x & 31;
    if (wv >= N_NODES) return;
    int beg = g_off[wv];
    int end = (wv == N_NODES - 1) ? E_EDGES : g_off[wv + 1];
    bool act = lane < 10;

    float4 a0 = make_float4(0.f, 0.f, 0.f, 0.f);
    float4 a1 = make_float4(0.f, 0.f, 0.f, 0.f);
    float4 a2 = make_float4(0.f, 0.f, 0.f, 0.f);
    float4 a3 = make_float4(0.f, 0.f, 0.f, 0.f);
    int j = beg;
    for (; j + 4 <= end; j += 4) {
        int s0 = g_esrc[j], s1 = g_esrc[j + 1], s2 = g_esrc[j + 2], s3 = g_esrc[j + 3];
        float w0 = g_ewp[j], w1 = g_ewp[j + 1], w2 = g_ewp[j + 2], w3 = g_ewp[j + 3];
        if (act) {
            uint2 q0 = ((const uint2*)(g_m2h + (size_t)s0 * 20))[lane];
            uint2 q1 = ((const uint2*)(g_m2h + (size_t)s1 * 20))[lane];
            uint2 q2 = ((const uint2*)(g_m2h + (size_t)s2 * 20))[lane];
            uint2 q3 = ((const uint2*)(g_m2h + (size_t)s3 * 20))[lane];
            float2 u, v;
            u = __half22float2(*(__half2*)&q0.x); v = __half22float2(*(__half2*)&q0.y);
            a0.x += u.x * w0; a0.y += u.y * w0; a0.z += v.x * w0; a0.w += v.y * w0;
            u = __half22float2(*(__half2*)&q1.x); v = __half22float2(*(__half2*)&q1.y);
            a1.x += u.x * w1; a1.y += u.y * w1; a1.z += v.x * w1; a1.w += v.y * w1;
            u = __half22float2(*(__half2*)&q2.x); v = __half22float2(*(__half2*)&q2.y);
            a2.x += u.x * w2; a2.y += u.y * w2; a2.z += v.x * w2; a2.w += v.y * w2;
            u = __half22float2(*(__half2*)&q3.x); v = __half22float2(*(__half2*)&q3.y);
            a3.x += u.x * w3; a3.y += u.y * w3; a3.z += v.x * w3; a3.w += v.y * w3;
        }
    }
    for (; j < end; j++) {
        int s0 = g_esrc[j];
        float w0 = g_ewp[j];
        if (act) {
            uint2 q0 = ((const uint2*)(g_m2h + (size_t)s0 * 20))[lane];
            float2 u = __half22float2(*(__half2*)&q0.x);
            float2 v = __half22float2(*(__half2*)&q0.y);
            a0.x += u.x * w0; a0.y += u.y * w0; a0.z += v.x * w0; a0.w += v.y * w0;
        }
    }
    float4 x = make_float4(a0.x + a1.x + a2.x + a3.x, a0.y + a1.y + a2.y + a3.y,
                           a0.z + a1.z + a2.z + a3.z, a0.w + a1.w + a2.w + a3.w);
    if (act) {
        float4 bb = ((const float4*)b2)[lane];
        x.x += bb.x; x.y += bb.y; x.z += bb.z; x.w += bb.w;
    }

    float m = act ? fmaxf(fmaxf(x.x, x.y), fmaxf(x.z, x.w)) : -1e30f;
    #pragma unroll
    for (int o = 16; o; o >>= 1) m = fmaxf(m, __shfl_xor_sync(0xFFFFFFFFu, m, o));

    float s = act ? (__expf(x.x - m) + __expf(x.y - m) +
                     __expf(x.z - m) + __expf(x.w - m)) : 0.f;
    #pragma unroll
    for (int o = 16; o; o >>= 1) s += __shfl_xor_sync(0xFFFFFFFFu, s, o);

    float lse = m + __logf(s);
    if (act) {
        x.x -= lse; x.y -= lse; x.z -= lse; x.w -= lse;
        ((float4*)(out + (size_t)wv * F_OUT))[lane] = x;
    }
}

// ============================================================================
extern "C" void kernel_launch(void* const* d_in, const int* in_sizes, int n_in,
                              void* d_out, int out_size) {
    const float* X   = (const float*)d_in[0];        // [100000,512]
    const int*   EI  = (const int*)d_in[1];          // [2,1600000] int32
    const float* EW  = (const float*)d_in[2];        // [1600000]
    const float* W1  = (const float*)d_in[3];        // [512,128]
    const float* B1  = (const float*)d_in[4];        // [128]
    const float* W2  = (const float*)d_in[5];        // [128,40]
    const float* B2  = (const float*)d_in[6];        // [40]
    float*       OUT = (float*)d_out;                // [100000,40]

    // one-time setup (first call is outside graph capture)
    static cudaStream_t s2 = nullptr;
    static cudaEvent_t evFork = nullptr, evW1 = nullptr, evJoin = nullptr;
    if (!s2) {
        cudaStreamCreateWithFlags(&s2, cudaStreamNonBlocking);
        cudaEventCreateWithFlags(&evFork, cudaEventDisableTiming);
        cudaEventCreateWithFlags(&evW1, cudaEventDisableTiming);
        cudaEventCreateWithFlags(&evJoin, cudaEventDisableTiming);
        cudaFuncSetAttribute(gemm1_mma,
                             cudaFuncAttributeMaxDynamicSharedMemorySize, G1_SMEM);
        cudaFuncSetAttribute(gemm2_mma,
                             cudaFuncAttributeMaxDynamicSharedMemorySize, G2M_SMEM);
    }

    const int NB_SCAN = (N_NODES + 1023) / 1024;     // 98
    const int EB = E_EDGES / 256;                    // 6250 (exact)

    void* degPtr = nullptr;
    cudaGetSymbolAddress(&degPtr, g_deg);

    // ---- fork: weight prep + CSR binning on s2, overlapped with gemm1 ----
    cudaEventRecord(evFork, 0);
    cudaStreamWaitEvent(s2, evFork, 0);

    prep_w1<<<128, 256, 0, s2>>>(W1);
    cudaEventRecord(evW1, s2);                        // gemm1 needs only this
    prep_w2<<<10, 256, 0, s2>>>(W2);
    cudaMemsetAsync(degPtr, 0, N_NODES * sizeof(int), s2);
    bin_count<<<EB, 256, 0, s2>>>(EI);
    scanA<<<NB_SCAN, 256, 0, s2>>>();
    scanB<<<1, 128, 0, s2>>>(NB_SCAN);
    scanC<<<NB_SCAN, 256, 0, s2>>>();
    bin_fill<<<EB, 256, 0, s2>>>(EI, EW);
    cudaEventRecord(evJoin, s2);

    // stream 0: GEMM1 (waits only on W1 prep)
    cudaStreamWaitEvent(0, evW1, 0);
    gemm1_mma<<<(N_NODES + 127) / 128, 256, G1_SMEM>>>(X);

    // ---- join ----
    cudaStreamWaitEvent(0, evJoin, 0);

    // Agg1 (fused b1 + relu): agg1 = relu(S(m1) + b1)
    agg1_kernel<<<(N_NODES + 7) / 8, 256>>>(B1);

    // GEMM2 (tensor): m2 = agg1 @ W2, fp16 out
    gemm2_mma<<<(N_NODES + 127) / 128, 256, G2M_SMEM>>>();

    // Agg2 + b2 + log_softmax fused, writes d_out
    agg2_ls_kernel<<<(N_NODES + 7) / 8, 256>>>(B2, OUT);
}